// round 4
// baseline (speedup 1.0000x reference)
#include <cuda_runtime.h>
#include <math.h>

#define NN 50000
#define NE 800000
#define FIN 11

// ---------------- scratch (device globals; no allocation allowed) ----------------
__device__ float g_h[(size_t)NN * 512];     // GEMM output (pre-bias h)
__device__ float g_x[(size_t)NN * 512];     // layer input / aggregated output
__device__ float g_hfin[(size_t)NN * 128];  // final node embeddings
__device__ float g_asrc[NN * 4];
__device__ float g_adst[NN * 4];
__device__ int   g_deg[NN];
__device__ int   g_rowptr[NN + 1];
__device__ int   g_cursor[NN];
__device__ int   g_eid[NE];
__device__ int   g_src[NE];
__device__ int   g_dst[NE];
__device__ float g_gsum[128];
__device__ int   g_is64;

// ---------------- dtype detection for edge_index ----------------
// int64 little-endian with values in [0, 50000) => every odd int32 word is 0.
// int32 data => odd words are random node ids; 256 consecutive zeros ~ impossible.
__global__ void k_detect(const int* __restrict__ ei32) {
    int nz = 0;
    for (int i = 0; i < 256; i++)
        if (ei32[2 * i + 1] != 0) nz = 1;
    g_is64 = nz ? 0 : 1;
}

// ---------------- graph prep ----------------
__global__ void k_init() {
    int i = blockIdx.x * blockDim.x + threadIdx.x;
    if (i < NN) g_deg[i] = 0;
    if (i < 128) g_gsum[i] = 0.f;
}

__global__ void k_prep(const void* __restrict__ ei) {
    int e = blockIdx.x * blockDim.x + threadIdx.x;
    if (e >= NE) return;
    int s, d;
    if (g_is64) {
        const long long* p = (const long long*)ei;
        s = (int)p[e];
        d = (int)p[NE + e];
    } else {
        const int* p = (const int*)ei;
        s = p[e];
        d = p[NE + e];
    }
    s = min(max(s, 0), NN - 1);
    d = min(max(d, 0), NN - 1);
    g_src[e] = s;
    g_dst[e] = d;
    atomicAdd(&g_deg[d], 1);
}

__global__ void k_scan() {
    const int CH = 49;  // 1024*49 = 50176 >= NN
    int t = threadIdx.x;
    int start = t * CH;
    int end = min(start + CH, NN);
    int sum = 0;
    for (int i = start; i < end; i++) sum += g_deg[i];
    __shared__ int sh[1024];
    sh[t] = sum;
    __syncthreads();
    for (int o = 1; o < 1024; o <<= 1) {
        int v = (t >= o) ? sh[t - o] : 0;
        __syncthreads();
        sh[t] += v;
        __syncthreads();
    }
    int pre = (t == 0) ? 0 : sh[t - 1];
    for (int i = start; i < end; i++) {
        g_rowptr[i] = pre;
        g_cursor[i] = pre;
        pre += g_deg[i];
    }
    if (t == 1023) g_rowptr[NN] = sh[1023];
}

__global__ void k_scatter() {
    int e = blockIdx.x * blockDim.x + threadIdx.x;
    if (e >= NE) return;
    int d = g_dst[e];
    int pos = atomicAdd(&g_cursor[d], 1);
    g_eid[pos] = e;
}

// ---------------- layer-1 GEMM (K=11, tiny): x @ W1 -> g_h ----------------
__global__ void k_gemm_l1(const float* __restrict__ x, const float* __restrict__ W) {
    int n = blockIdx.x;
    int c = threadIdx.x;  // 512
    float acc = 0.f;
#pragma unroll
    for (int k = 0; k < FIN; k++) acc += x[n * FIN + k] * W[k * 512 + c];
    g_h[(size_t)n * 512 + c] = acc;
}

// ---------------- attention logits (reads g_h) ----------------
template <int H>
__global__ void k_alpha(const float* __restrict__ as, const float* __restrict__ ad) {
    int warp = (blockIdx.x * blockDim.x + threadIdx.x) >> 5;
    int lane = threadIdx.x & 31;
    if (warp >= NN) return;
    const int CH = H * 128;
    const float* hr = g_h + (size_t)warp * CH;
#pragma unroll
    for (int hh = 0; hh < H; hh++) {
        float s1 = 0.f, s2 = 0.f;
#pragma unroll
        for (int j = 0; j < 4; j++) {
            int c = hh * 128 + lane + 32 * j;
            float v = hr[c];
            s1 += v * as[c];
            s2 += v * ad[c];
        }
        for (int o = 16; o > 0; o >>= 1) {
            s1 += __shfl_down_sync(0xffffffffu, s1, o);
            s2 += __shfl_down_sync(0xffffffffu, s2, o);
        }
        if (lane == 0) {
            g_asrc[warp * H + hh] = s1;
            g_adst[warp * H + hh] = s2;
        }
    }
}

// ---------------- fused segment softmax + aggregation (CSR, block per dst) ----------------
// Reads g_h; writes g_x (FIN_OUT=false) or g_hfin (FIN_OUT=true).
template <int H, bool ELU, bool FIN_OUT>
__global__ void k_agg(const float* __restrict__ bias) {
    const int CH = H * 128;
    int n = blockIdx.x;
    int tid = threadIdx.x;  // 128
    int beg = g_rowptr[n];
    int end = g_rowptr[n + 1];

    float adn[H];
#pragma unroll
    for (int hh = 0; hh < H; hh++) adn[hh] = g_adst[n * H + hh];

    __shared__ float red[128];
    __shared__ float smax[H];
    __shared__ float ssum[H];
    __shared__ int ssrc[128];
    __shared__ float wsh[H][128];

    // pass 1: max per head
    float mloc[H];
#pragma unroll
    for (int hh = 0; hh < H; hh++) mloc[hh] = -INFINITY;
    for (int i = beg + tid; i < end; i += 128) {
        int s = g_src[g_eid[i]];
#pragma unroll
        for (int hh = 0; hh < H; hh++) {
            float v = g_asrc[s * H + hh] + adn[hh];
            v = fmaxf(v, 0.2f * v);  // leaky relu
            mloc[hh] = fmaxf(mloc[hh], v);
        }
    }
#pragma unroll
    for (int hh = 0; hh < H; hh++) {
        red[tid] = mloc[hh];
        __syncthreads();
        for (int o = 64; o > 0; o >>= 1) {
            if (tid < o) red[tid] = fmaxf(red[tid], red[tid + o]);
            __syncthreads();
        }
        if (tid == 0) smax[hh] = red[0];
        __syncthreads();
    }

    // pass 2: sum of exp
    float sloc[H];
#pragma unroll
    for (int hh = 0; hh < H; hh++) sloc[hh] = 0.f;
    for (int i = beg + tid; i < end; i += 128) {
        int s = g_src[g_eid[i]];
#pragma unroll
        for (int hh = 0; hh < H; hh++) {
            float v = g_asrc[s * H + hh] + adn[hh];
            v = fmaxf(v, 0.2f * v);
            sloc[hh] += __expf(v - smax[hh]);
        }
    }
#pragma unroll
    for (int hh = 0; hh < H; hh++) {
        red[tid] = sloc[hh];
        __syncthreads();
        for (int o = 64; o > 0; o >>= 1) {
            if (tid < o) red[tid] += red[tid + o];
            __syncthreads();
        }
        if (tid == 0) ssum[hh] = red[0];
        __syncthreads();
    }

    // pass 3: weighted accumulation of h[src]
    float acc[H];
#pragma unroll
    for (int hh = 0; hh < H; hh++) acc[hh] = 0.f;
    for (int tb = beg; tb < end; tb += 128) {
        int i = tb + tid;
        if (i < end) {
            int s = g_src[g_eid[i]];
            ssrc[tid] = s;
#pragma unroll
            for (int hh = 0; hh < H; hh++) {
                float v = g_asrc[s * H + hh] + adn[hh];
                v = fmaxf(v, 0.2f * v);
                wsh[hh][tid] = __expf(v - smax[hh]);
            }
        }
        __syncthreads();
        int cnt = min(128, end - tb);
        for (int j = 0; j < cnt; j++) {
            int s = ssrc[j];
            const float* hr = g_h + (size_t)s * CH;
#pragma unroll
            for (int hh = 0; hh < H; hh++) acc[hh] += wsh[hh][j] * hr[hh * 128 + tid];
        }
        __syncthreads();
    }

    float* out = FIN_OUT ? g_hfin : g_x;
#pragma unroll
    for (int hh = 0; hh < H; hh++) {
        float denom = ssum[hh];
        float val = (denom > 0.f) ? acc[hh] / denom : 0.f;
        val += bias[hh * 128 + tid];
        if (ELU) val = (val > 0.f) ? val : (__expf(val) - 1.f);
        out[(size_t)n * CH + hh * 128 + tid] = val;
    }
}

// ---------------- SGEMM: g_h[M,N] = g_x[M,K] @ B[K,N], row-major ----------------
__global__ __launch_bounds__(256) void k_sgemm(const float* __restrict__ B, int M, int N,
                                               int K) {
    __shared__ float As[8][128];
    __shared__ float Bs[8][128];
    int tid = threadIdx.x;
    int bn = blockIdx.x, bm = blockIdx.y;
    int rowA = tid >> 1;
    int colA = (tid & 1) * 4;
    int rowB = tid >> 5;
    int colB = (tid & 31) * 4;
    int ty = (tid >> 4) * 8;
    int tx = (tid & 15) * 8;

    float acc[8][8];
#pragma unroll
    for (int i = 0; i < 8; i++)
#pragma unroll
        for (int j = 0; j < 8; j++) acc[i][j] = 0.f;

    const float* Ap = g_x + (size_t)(bm * 128 + rowA) * K + colA;
    const float* Bp = B + (size_t)rowB * N + bn * 128 + colB;
    bool aval = (bm * 128 + rowA) < M;

    for (int k0 = 0; k0 < K; k0 += 8) {
        float4 a4 = aval ? *(const float4*)Ap : make_float4(0.f, 0.f, 0.f, 0.f);
        As[colA + 0][rowA] = a4.x;
        As[colA + 1][rowA] = a4.y;
        As[colA + 2][rowA] = a4.z;
        As[colA + 3][rowA] = a4.w;
        float4 b4 = *(const float4*)Bp;
        *(float4*)&Bs[rowB][colB] = b4;
        __syncthreads();
#pragma unroll
        for (int k = 0; k < 8; k++) {
            float ra[8], rb[8];
            *(float4*)(ra) = *(const float4*)&As[k][ty];
            *(float4*)(ra + 4) = *(const float4*)&As[k][ty + 4];
            *(float4*)(rb) = *(const float4*)&Bs[k][tx];
            *(float4*)(rb + 4) = *(const float4*)&Bs[k][tx + 4];
#pragma unroll
            for (int i = 0; i < 8; i++)
#pragma unroll
                for (int j = 0; j < 8; j++) acc[i][j] += ra[i] * rb[j];
        }
        __syncthreads();
        Ap += 8;
        Bp += (size_t)8 * N;
    }

#pragma unroll
    for (int i = 0; i < 8; i++) {
        int r = bm * 128 + ty + i;
        if (r < M) {
            float* Cp = g_h + (size_t)r * N + bn * 128 + tx;
            *(float4*)Cp = make_float4(acc[i][0], acc[i][1], acc[i][2], acc[i][3]);
            *((float4*)Cp + 1) = make_float4(acc[i][4], acc[i][5], acc[i][6], acc[i][7]);
        }
    }
}

// ---------------- mean over nodes ----------------
__global__ void k_mean() {
    int c = threadIdx.x;  // 128
    int r0 = blockIdx.x * 128;
    int r1 = min(r0 + 128, NN);
    float s = 0.f;
    for (int r = r0; r < r1; r++) s += g_hfin[(size_t)r * 128 + c];
    atomicAdd(&g_gsum[c], s);
}

// ---------------- policy / value heads ----------------
__global__ void k_head(const int* __restrict__ cni, const float* __restrict__ pw1,
                       const float* __restrict__ pb1, const float* __restrict__ pw2,
                       const float* __restrict__ pb2, const float* __restrict__ vw1,
                       const float* __restrict__ vb1, const float* __restrict__ vw2,
                       const float* __restrict__ vb2, float* __restrict__ out) {
    __shared__ float comb[128], hid1[128], red[128];
    int t = threadIdx.x;  // 128
    int idx = cni[0];
    idx = min(max(idx, 0), NN - 1);
    comb[t] = g_gsum[t] * (1.0f / (float)NN) + g_hfin[(size_t)idx * 128 + t];
    __syncthreads();

    // policy
    float a = 0.f;
    for (int c = 0; c < 128; c++) a += comb[c] * pw1[c * 128 + t];
    a += pb1[t];
    a = fmaxf(a, 0.f);
    hid1[t] = a;
    __syncthreads();
    if (t < 6) {
        float p = pb2[t];
        for (int j = 0; j < 128; j++) p += hid1[j] * pw2[j * 6 + t];
        out[t] = p;
    }
    __syncthreads();

    // value
    float b = 0.f;
    for (int c = 0; c < 128; c++) b += comb[c] * vw1[c * 128 + t];
    b += vb1[t];
    b = fmaxf(b, 0.f);
    red[t] = b * vw2[t];
    __syncthreads();
    for (int o = 64; o > 0; o >>= 1) {
        if (t < o) red[t] += red[t + o];
        __syncthreads();
    }
    if (t == 0) out[6] = red[0] + vb2[0];
}

// ---------------- driver (pure kernel launches; graph-capturable) ----------------
extern "C" void kernel_launch(void* const* d_in, const int* in_sizes, int n_in,
                              void* d_out, int out_size) {
    const float* x = (const float*)d_in[0];
    const void* ei = (const void*)d_in[1];
    const int* cni = (const int*)d_in[2];
    const float* W1 = (const float*)d_in[3];
    const float* as1 = (const float*)d_in[4];
    const float* ad1 = (const float*)d_in[5];
    const float* b1 = (const float*)d_in[6];
    const float* W2 = (const float*)d_in[7];
    const float* as2 = (const float*)d_in[8];
    const float* ad2 = (const float*)d_in[9];
    const float* b2 = (const float*)d_in[10];
    const float* W3 = (const float*)d_in[11];
    const float* as3 = (const float*)d_in[12];
    const float* ad3 = (const float*)d_in[13];
    const float* b3 = (const float*)d_in[14];
    const float* pw1 = (const float*)d_in[15];
    const float* pb1 = (const float*)d_in[16];
    const float* pw2 = (const float*)d_in[17];
    const float* pb2 = (const float*)d_in[18];
    const float* vw1 = (const float*)d_in[19];
    const float* vb1 = (const float*)d_in[20];
    const float* vw2 = (const float*)d_in[21];
    const float* vb2 = (const float*)d_in[22];
    float* out = (float*)d_out;

    // graph prep (CSR by dst)
    k_detect<<<1, 1>>>((const int*)ei);
    k_init<<<(NN + 255) / 256, 256>>>();
    k_prep<<<(NE + 255) / 256, 256>>>(ei);
    k_scan<<<1, 1024>>>();
    k_scatter<<<(NE + 255) / 256, 256>>>();

    // layer 1: 11 -> 4x128
    k_gemm_l1<<<NN, 512>>>(x, W1);
    k_alpha<4><<<(NN * 32 + 255) / 256, 256>>>(as1, ad1);
    k_agg<4, true, false><<<NN, 128>>>(b1);

    // layer 2: 512 -> 4x128
    {
        dim3 grid(4, (NN + 127) / 128);
        k_sgemm<<<grid, 256>>>(W2, NN, 512, 512);
    }
    k_alpha<4><<<(NN * 32 + 255) / 256, 256>>>(as2, ad2);
    k_agg<4, true, false><<<NN, 128>>>(b2);

    // layer 3: 512 -> 1x128
    {
        dim3 grid(1, (NN + 127) / 128);
        k_sgemm<<<grid, 256>>>(W3, NN, 128, 512);
    }
    k_alpha<1><<<(NN * 32 + 255) / 256, 256>>>(as3, ad3);
    k_agg<1, false, true><<<NN, 128>>>(b3);

    // readout + heads
    k_mean<<<(NN + 127) / 128, 128>>>();
    k_head<<<1, 128>>>(cni, pw1, pb1, pw2, pb2, vw1, vb1, vw2, vb2, out);
}

// round 6
// speedup vs baseline: 1.0935x; 1.0935x over previous
#include <cuda_runtime.h>
#include <math.h>

#define NN 50000
#define NE 800000
#define FIN 11
#define NP 196  // ceil(NN/256)

// ---------------- scratch ----------------
__device__ float g_h[(size_t)NN * 512];
__device__ float g_x[(size_t)NN * 512];
__device__ float g_hfin[(size_t)NN * 128];
__device__ float g_asrc[NN * 4];
__device__ float g_adst[NN * 4];
__device__ int   g_deg[NN];
__device__ int   g_rowptr[NN + 1];
__device__ int   g_cursor[NN];
__device__ int   g_csrc[NE];   // CSR-ordered src node per slot
__device__ int   g_src[NE];
__device__ int   g_dst[NE];
__device__ int   g_part[NP];
__device__ float g_gsum[128];
__device__ int   g_is64;

// ---------------- dtype detection (parallel) ----------------
__global__ void k_detect(const int* __restrict__ ei32) {
    __shared__ int nz;
    if (threadIdx.x == 0) nz = 0;
    __syncthreads();
    if (ei32[2 * threadIdx.x + 1] != 0) atomicOr(&nz, 1);
    __syncthreads();
    if (threadIdx.x == 0) g_is64 = nz ? 0 : 1;
}

// ---------------- graph prep ----------------
__global__ void k_init() {
    int i = blockIdx.x * blockDim.x + threadIdx.x;
    if (i < NN) g_deg[i] = 0;
    if (i < 128) g_gsum[i] = 0.f;
}

__global__ void k_prep(const void* __restrict__ ei) {
    int e = blockIdx.x * blockDim.x + threadIdx.x;
    if (e >= NE) return;
    int s, d;
    if (g_is64) {
        const long long* p = (const long long*)ei;
        s = (int)p[e];
        d = (int)p[NE + e];
    } else {
        const int* p = (const int*)ei;
        s = p[e];
        d = p[NE + e];
    }
    s = min(max(s, 0), NN - 1);
    d = min(max(d, 0), NN - 1);
    g_src[e] = s;
    g_dst[e] = d;
    atomicAdd(&g_deg[d], 1);
}

// two-level scan: per-chunk sums -> scan of sums -> local scans
__global__ void k_scan1() {
    __shared__ int sh[256];
    int t = threadIdx.x;
    int i = blockIdx.x * 256 + t;
    sh[t] = (i < NN) ? g_deg[i] : 0;
    __syncthreads();
    for (int o = 128; o > 0; o >>= 1) {
        if (t < o) sh[t] += sh[t + o];
        __syncthreads();
    }
    if (t == 0) g_part[blockIdx.x] = sh[0];
}

__global__ void k_scan2() {
    __shared__ int sh[256];
    int t = threadIdx.x;
    int v = (t < NP) ? g_part[t] : 0;
    sh[t] = v;
    __syncthreads();
    for (int o = 1; o < 256; o <<= 1) {
        int u = (t >= o) ? sh[t - o] : 0;
        __syncthreads();
        sh[t] += u;
        __syncthreads();
    }
    if (t < NP) g_part[t] = sh[t] - v;  // exclusive
}

__global__ void k_scan3() {
    __shared__ int sh[256];
    int t = threadIdx.x;
    int i = blockIdx.x * 256 + t;
    int v = (i < NN) ? g_deg[i] : 0;
    sh[t] = v;
    __syncthreads();
    for (int o = 1; o < 256; o <<= 1) {
        int u = (t >= o) ? sh[t - o] : 0;
        __syncthreads();
        sh[t] += u;
        __syncthreads();
    }
    if (i < NN) {
        int val = g_part[blockIdx.x] + sh[t] - v;
        g_rowptr[i] = val;
        g_cursor[i] = val;
        if (i == NN - 1) g_rowptr[NN] = val + v;
    }
}

__global__ void k_scatter() {
    int e = blockIdx.x * blockDim.x + threadIdx.x;
    if (e >= NE) return;
    int d = g_dst[e];
    int pos = atomicAdd(&g_cursor[d], 1);
    g_csrc[pos] = g_src[e];
}

// ---------------- layer-1 GEMM (K=11) ----------------
__global__ void k_gemm_l1(const float* __restrict__ x, const float* __restrict__ W) {
    int n = blockIdx.x;
    int c = threadIdx.x;  // 512
    float acc = 0.f;
#pragma unroll
    for (int k = 0; k < FIN; k++) acc += x[n * FIN + k] * W[k * 512 + c];
    g_h[(size_t)n * 512 + c] = acc;
}

// ---------------- attention logits ----------------
template <int H>
__global__ void k_alpha(const float* __restrict__ as, const float* __restrict__ ad) {
    int warp = (blockIdx.x * blockDim.x + threadIdx.x) >> 5;
    int lane = threadIdx.x & 31;
    if (warp >= NN) return;
    const int CH = H * 128;
    const float* hr = g_h + (size_t)warp * CH;
#pragma unroll
    for (int hh = 0; hh < H; hh++) {
        float s1 = 0.f, s2 = 0.f;
#pragma unroll
        for (int j = 0; j < 4; j++) {
            int c = hh * 128 + lane + 32 * j;
            float v = hr[c];
            s1 += v * as[c];
            s2 += v * ad[c];
        }
        for (int o = 16; o > 0; o >>= 1) {
            s1 += __shfl_down_sync(0xffffffffu, s1, o);
            s2 += __shfl_down_sync(0xffffffffu, s2, o);
        }
        if (lane == 0) {
            g_asrc[warp * H + hh] = s1;
            g_adst[warp * H + hh] = s2;
        }
    }
}

// ---------------- fused segment softmax + aggregation ----------------
template <int H, bool ELU, bool FIN_OUT>
__global__ void k_agg(const float* __restrict__ bias) {
    const int CH = H * 128;
    int n = blockIdx.x;
    int tid = threadIdx.x;  // 128
    int beg = g_rowptr[n];
    int end = g_rowptr[n + 1];

    float adn[H];
#pragma unroll
    for (int hh = 0; hh < H; hh++) adn[hh] = g_adst[n * H + hh];

    __shared__ float red[128];
    __shared__ float smax[H];
    __shared__ float ssum[H];
    __shared__ int ssrc[128];
    __shared__ float wsh[H][128];

    float mloc[H];
#pragma unroll
    for (int hh = 0; hh < H; hh++) mloc[hh] = -INFINITY;
    for (int i = beg + tid; i < end; i += 128) {
        int s = g_csrc[i];
#pragma unroll
        for (int hh = 0; hh < H; hh++) {
            float v = g_asrc[s * H + hh] + adn[hh];
            v = fmaxf(v, 0.2f * v);
            mloc[hh] = fmaxf(mloc[hh], v);
        }
    }
#pragma unroll
    for (int hh = 0; hh < H; hh++) {
        red[tid] = mloc[hh];
        __syncthreads();
        for (int o = 64; o > 0; o >>= 1) {
            if (tid < o) red[tid] = fmaxf(red[tid], red[tid + o]);
            __syncthreads();
        }
        if (tid == 0) smax[hh] = red[0];
        __syncthreads();
    }

    float sloc[H];
#pragma unroll
    for (int hh = 0; hh < H; hh++) sloc[hh] = 0.f;
    for (int i = beg + tid; i < end; i += 128) {
        int s = g_csrc[i];
#pragma unroll
        for (int hh = 0; hh < H; hh++) {
            float v = g_asrc[s * H + hh] + adn[hh];
            v = fmaxf(v, 0.2f * v);
            sloc[hh] += __expf(v - smax[hh]);
        }
    }
#pragma unroll
    for (int hh = 0; hh < H; hh++) {
        red[tid] = sloc[hh];
        __syncthreads();
        for (int o = 64; o > 0; o >>= 1) {
            if (tid < o) red[tid] += red[tid + o];
            __syncthreads();
        }
        if (tid == 0) ssum[hh] = red[0];
        __syncthreads();
    }

    float acc[H];
#pragma unroll
    for (int hh = 0; hh < H; hh++) acc[hh] = 0.f;
    for (int tb = beg; tb < end; tb += 128) {
        int i = tb + tid;
        if (i < end) {
            int s = g_csrc[i];
            ssrc[tid] = s;
#pragma unroll
            for (int hh = 0; hh < H; hh++) {
                float v = g_asrc[s * H + hh] + adn[hh];
                v = fmaxf(v, 0.2f * v);
                wsh[hh][tid] = __expf(v - smax[hh]);
            }
        }
        __syncthreads();
        int cnt = min(128, end - tb);
        for (int j = 0; j < cnt; j++) {
            int s = ssrc[j];
            const float* hr = g_h + (size_t)s * CH;
#pragma unroll
            for (int hh = 0; hh < H; hh++) acc[hh] += wsh[hh][j] * hr[hh * 128 + tid];
        }
        __syncthreads();
    }

    float* out = FIN_OUT ? g_hfin : g_x;
#pragma unroll
    for (int hh = 0; hh < H; hh++) {
        float denom = ssum[hh];
        float val = (denom > 0.f) ? acc[hh] / denom : 0.f;
        val += bias[hh * 128 + tid];
        if (ELU) val = (val > 0.f) ? val : (__expf(val) - 1.f);
        out[(size_t)n * CH + hh * 128 + tid] = val;
    }
}

// ---------------- 3xTF32 tensor-core GEMM: g_h = g_x @ B ----------------
__device__ __forceinline__ unsigned f2tf(float x) {
    unsigned u;
    asm("cvt.rna.tf32.f32 %0, %1;" : "=r"(u) : "f"(x));
    return u;
}

__device__ __forceinline__ void mma_tf32(float* c, unsigned a0, unsigned a1, unsigned a2,
                                         unsigned a3, unsigned b0, unsigned b1) {
    asm volatile(
        "mma.sync.aligned.m16n8k8.row.col.f32.tf32.tf32.f32 "
        "{%0,%1,%2,%3}, {%4,%5,%6,%7}, {%8,%9}, {%0,%1,%2,%3};"
        : "+f"(c[0]), "+f"(c[1]), "+f"(c[2]), "+f"(c[3])
        : "r"(a0), "r"(a1), "r"(a2), "r"(a3), "r"(b0), "r"(b1));
}

#define BK 16
__global__ __launch_bounds__(256) void k_tfgemm(const float* __restrict__ B, int M, int N,
                                                int K) {
    __shared__ float As[128][20];  // [m][k], pad 20 for conflict-free frag loads
    __shared__ float Bs[128][20];  // [n][k]
    int tid = threadIdx.x;
    int bn = blockIdx.x, bm = blockIdx.y;
    int lane = tid & 31;
    int warp = tid >> 5;
    int gid = lane >> 2;   // 0..7
    int tq = lane & 3;     // 0..3
    int wm = (warp & 1) * 64;   // warp m offset
    int wn = (warp >> 1) * 32;  // warp n offset

    int rowA = tid >> 2;          // 0..63 (+64)
    int colA = (tid & 3) * 4;
    int rowB = tid >> 5;          // 0..7 (+8)
    int colB = (tid & 31) * 4;

    float acc[4][4][4];
#pragma unroll
    for (int i = 0; i < 4; i++)
#pragma unroll
        for (int j = 0; j < 4; j++)
#pragma unroll
            for (int r = 0; r < 4; r++) acc[i][j][r] = 0.f;

    int mrow0 = bm * 128 + rowA;
    int mrow1 = mrow0 + 64;
    bool v0 = mrow0 < M, v1 = mrow1 < M;

    for (int k0 = 0; k0 < K; k0 += BK) {
        float4 a0 = v0 ? *(const float4*)(g_x + (size_t)mrow0 * K + k0 + colA)
                       : make_float4(0.f, 0.f, 0.f, 0.f);
        float4 a1 = v1 ? *(const float4*)(g_x + (size_t)mrow1 * K + k0 + colA)
                       : make_float4(0.f, 0.f, 0.f, 0.f);
        As[rowA][colA + 0] = a0.x; As[rowA][colA + 1] = a0.y;
        As[rowA][colA + 2] = a0.z; As[rowA][colA + 3] = a0.w;
        As[rowA + 64][colA + 0] = a1.x; As[rowA + 64][colA + 1] = a1.y;
        As[rowA + 64][colA + 2] = a1.z; As[rowA + 64][colA + 3] = a1.w;
        float4 b0 = *(const float4*)(B + (size_t)(k0 + rowB) * N + bn * 128 + colB);
        float4 b1 = *(const float4*)(B + (size_t)(k0 + rowB + 8) * N + bn * 128 + colB);
        Bs[colB + 0][rowB] = b0.x; Bs[colB + 1][rowB] = b0.y;
        Bs[colB + 2][rowB] = b0.z; Bs[colB + 3][rowB] = b0.w;
        Bs[colB + 0][rowB + 8] = b1.x; Bs[colB + 1][rowB + 8] = b1.y;
        Bs[colB + 2][rowB + 8] = b1.z; Bs[colB + 3][rowB + 8] = b1.w;
        __syncthreads();

#pragma unroll
        for (int kk = 0; kk < BK; kk += 8) {
            unsigned ah[4][4], al[4][4], bh[4][2], bl[4][2];
#pragma unroll
            for (int mi = 0; mi < 4; mi++) {
                int mb = wm + mi * 16;
                float f0 = As[mb + gid][kk + tq];
                float f1 = As[mb + gid + 8][kk + tq];
                float f2 = As[mb + gid][kk + tq + 4];
                float f3 = As[mb + gid + 8][kk + tq + 4];
                ah[mi][0] = f2tf(f0); al[mi][0] = f2tf(f0 - __uint_as_float(ah[mi][0]));
                ah[mi][1] = f2tf(f1); al[mi][1] = f2tf(f1 - __uint_as_float(ah[mi][1]));
                ah[mi][2] = f2tf(f2); al[mi][2] = f2tf(f2 - __uint_as_float(ah[mi][2]));
                ah[mi][3] = f2tf(f3); al[mi][3] = f2tf(f3 - __uint_as_float(ah[mi][3]));
            }
#pragma unroll
            for (int ni = 0; ni < 4; ni++) {
                int nb = wn + ni * 8;
                float f0 = Bs[nb + gid][kk + tq];
                float f1 = Bs[nb + gid][kk + tq + 4];
                bh[ni][0] = f2tf(f0); bl[ni][0] = f2tf(f0 - __uint_as_float(bh[ni][0]));
                bh[ni][1] = f2tf(f1); bl[ni][1] = f2tf(f1 - __uint_as_float(bh[ni][1]));
            }
#pragma unroll
            for (int mi = 0; mi < 4; mi++)
#pragma unroll
                for (int ni = 0; ni < 4; ni++) {
                    mma_tf32(acc[mi][ni], ah[mi][0], ah[mi][1], ah[mi][2], ah[mi][3],
                             bh[ni][0], bh[ni][1]);
                    mma_tf32(acc[mi][ni], ah[mi][0], ah[mi][1], ah[mi][2], ah[mi][3],
                             bl[ni][0], bl[ni][1]);
                    mma_tf32(acc[mi][ni], al[mi][0], al[mi][1], al[mi][2], al[mi][3],
                             bh[ni][0], bh[ni][1]);
                }
        }
        __syncthreads();
    }

    // epilogue
#pragma unroll
    for (int mi = 0; mi < 4; mi++) {
        int r0 = bm * 128 + wm + mi * 16 + gid;
        int r1 = r0 + 8;
#pragma unroll
        for (int ni = 0; ni < 4; ni++) {
            int c = bn * 128 + wn + ni * 8 + tq * 2;
            if (r0 < M) {
                g_h[(size_t)r0 * N + c] = acc[mi][ni][0];
                g_h[(size_t)r0 * N + c + 1] = acc[mi][ni][1];
            }
            if (r1 < M) {
                g_h[(size_t)r1 * N + c] = acc[mi][ni][2];
                g_h[(size_t)r1 * N + c + 1] = acc[mi][ni][3];
            }
        }
    }
}

// ---------------- mean over nodes ----------------
__global__ void k_mean() {
    int c = threadIdx.x;  // 128
    int r0 = blockIdx.x * 128;
    int r1 = min(r0 + 128, NN);
    float s = 0.f;
    for (int r = r0; r < r1; r++) s += g_hfin[(size_t)r * 128 + c];
    atomicAdd(&g_gsum[c], s);
}

// ---------------- policy / value heads ----------------
__global__ void k_head(const int* __restrict__ cni, const float* __restrict__ pw1,
                       const float* __restrict__ pb1, const float* __restrict__ pw2,
                       const float* __restrict__ pb2, const float* __restrict__ vw1,
                       const float* __restrict__ vb1, const float* __restrict__ vw2,
                       const float* __restrict__ vb2, float* __restrict__ out) {
    __shared__ float comb[128], hid1[128], red[128];
    int t = threadIdx.x;  // 128
    int idx = cni[0];
    idx = min(max(idx, 0), NN - 1);
    comb[t] = g_gsum[t] * (1.0f / (float)NN) + g_hfin[(size_t)idx * 128 + t];
    __syncthreads();

    float a = 0.f;
    for (int c = 0; c < 128; c++) a += comb[c] * pw1[c * 128 + t];
    a += pb1[t];
    a = fmaxf(a, 0.f);
    hid1[t] = a;
    __syncthreads();
    if (t < 6) {
        float p = pb2[t];
        for (int j = 0; j < 128; j++) p += hid1[j] * pw2[j * 6 + t];
        out[t] = p;
    }
    __syncthreads();

    float b = 0.f;
    for (int c = 0; c < 128; c++) b += comb[c] * vw1[c * 128 + t];
    b += vb1[t];
    b = fmaxf(b, 0.f);
    red[t] = b * vw2[t];
    __syncthreads();
    for (int o = 64; o > 0; o >>= 1) {
        if (t < o) red[t] += red[t + o];
        __syncthreads();
    }
    if (t == 0) out[6] = red[0] + vb2[0];
}

// ---------------- driver ----------------
extern "C" void kernel_launch(void* const* d_in, const int* in_sizes, int n_in,
                              void* d_out, int out_size) {
    const float* x = (const float*)d_in[0];
    const void* ei = (const void*)d_in[1];
    const int* cni = (const int*)d_in[2];
    const float* W1 = (const float*)d_in[3];
    const float* as1 = (const float*)d_in[4];
    const float* ad1 = (const float*)d_in[5];
    const float* b1 = (const float*)d_in[6];
    const float* W2 = (const float*)d_in[7];
    const float* as2 = (const float*)d_in[8];
    const float* ad2 = (const float*)d_in[9];
    const float* b2 = (const float*)d_in[10];
    const float* W3 = (const float*)d_in[11];
    const float* as3 = (const float*)d_in[12];
    const float* ad3 = (const float*)d_in[13];
    const float* b3 = (const float*)d_in[14];
    const float* pw1 = (const float*)d_in[15];
    const float* pb1 = (const float*)d_in[16];
    const float* pw2 = (const float*)d_in[17];
    const float* pb2 = (const float*)d_in[18];
    const float* vw1 = (const float*)d_in[19];
    const float* vb1 = (const float*)d_in[20];
    const float* vw2 = (const float*)d_in[21];
    const float* vb2 = (const float*)d_in[22];
    float* out = (float*)d_out;

    // graph prep (CSR by dst)
    k_detect<<<1, 256>>>((const int*)ei);
    k_init<<<(NN + 255) / 256, 256>>>();
    k_prep<<<(NE + 255) / 256, 256>>>(ei);
    k_scan1<<<NP, 256>>>();
    k_scan2<<<1, 256>>>();
    k_scan3<<<NP, 256>>>();
    k_scatter<<<(NE + 255) / 256, 256>>>();

    // layer 1: 11 -> 4x128
    k_gemm_l1<<<NN, 512>>>(x, W1);
    k_alpha<4><<<(NN * 32 + 255) / 256, 256>>>(as1, ad1);
    k_agg<4, true, false><<<NN, 128>>>(b1);

    // layer 2: 512 -> 4x128
    {
        dim3 grid(4, (NN + 127) / 128);
        k_tfgemm<<<grid, 256>>>(W2, NN, 512, 512);
    }
    k_alpha<4><<<(NN * 32 + 255) / 256, 256>>>(as2, ad2);
    k_agg<4, true, false><<<NN, 128>>>(b2);

    // layer 3: 512 -> 1x128
    {
        dim3 grid(1, (NN + 127) / 128);
        k_tfgemm<<<grid, 256>>>(W3, NN, 128, 512);
    }
    k_alpha<1><<<(NN * 32 + 255) / 256, 256>>>(as3, ad3);
    k_agg<1, false, true><<<NN, 128>>>(b3);

    // readout + heads
    k_mean<<<(NN + 127) / 128, 128>>>();
    k_head<<<1, 128>>>(cni, pw1, pb1, pw2, pb2, vw1, vb1, vw2, vb2, out);
}